// round 15
// baseline (speedup 1.0000x reference)
#include <cuda_runtime.h>
#include <cuda_fp16.h>
#include <stdint.h>

// ---------------------------------------------------------------------------
// Problem constants
// ---------------------------------------------------------------------------
constexpr int BB = 4096;   // batch
constexpr int DD = 1024;   // ev_context dim
constexpr int HH = 1024;   // hidden
constexpr int TT = 50;     // timesteps

// ---------------------------------------------------------------------------
// Device scratch (no allocs)
// ---------------------------------------------------------------------------
__device__ float  g_h [2][(size_t)BB * HH];
__device__ __half g_hf[2][(size_t)BB * HH];
__device__ __half g_wf[(size_t)3 * HH * HH];
__device__ __half g_evf[(size_t)BB * DD];
__device__ __half g_wif[(size_t)HH * DD];
__device__ float  g_partial[(size_t)BB * TT * 2 * 16];   // [b][t][c][bu]

__device__ __forceinline__ float sigmoidf_(float x) {
    return 1.0f / (1.0f + __expf(-x));
}
__device__ __forceinline__ float tanh_fast(float x) {
    return 2.0f / (1.0f + __expf(-2.0f * x)) - 1.0f;
}

// ---------------------------------------------------------------------------
// PTX helpers (portable sm_80+ only; compute_103-safe)
// ---------------------------------------------------------------------------
__device__ __forceinline__ uint32_t smem_u32(const void* p) {
    uint32_t a;
    asm("{ .reg .u64 t; cvta.to.shared.u64 t, %1; cvt.u32.u64 %0, t; }"
        : "=r"(a) : "l"(p));
    return a;
}
__device__ __forceinline__ uint32_t swz(uint32_t o) { return o ^ ((o >> 3) & 0x70); }
__device__ __forceinline__ void cp_async16(uint32_t dst, const void* src) {
    asm volatile("cp.async.cg.shared.global [%0], [%1], 16;"
                 :: "r"(dst), "l"(src) : "memory");
}
__device__ __forceinline__ void cp_commit() {
    asm volatile("cp.async.commit_group;" ::: "memory");
}
__device__ __forceinline__ void cp_wait1() {
    asm volatile("cp.async.wait_group 1;" ::: "memory");
}
__device__ __forceinline__ void cp_wait0() {
    asm volatile("cp.async.wait_group 0;" ::: "memory");
}
__device__ __forceinline__ void ldsm4(uint32_t* r, uint32_t a) {
    asm volatile("ldmatrix.sync.aligned.m8n8.x4.shared.b16 {%0,%1,%2,%3}, [%4];"
                 : "=r"(r[0]), "=r"(r[1]), "=r"(r[2]), "=r"(r[3]) : "r"(a));
}
__device__ __forceinline__ void mma16816(float* d, const uint32_t* a, const uint32_t* b) {
    asm volatile(
        "mma.sync.aligned.m16n8k16.row.col.f32.f16.f16.f32 "
        "{%0,%1,%2,%3}, {%4,%5,%6,%7}, {%8,%9}, {%0,%1,%2,%3};"
        : "+f"(d[0]), "+f"(d[1]), "+f"(d[2]), "+f"(d[3])
        : "r"(a[0]), "r"(a[1]), "r"(a[2]), "r"(a[3]), "r"(b[0]), "r"(b[1]));
}

// ===========================================================================
// GRU step kernel (unchanged — at the legacy-HMMA issue ceiling, model-exact)
// ===========================================================================
constexpr int STAGE   = 32768;
constexpr int OFF_B   = 8192;
constexpr int NSTAGE  = 3;
constexpr int NCHUNK  = 16;                  // K=1024 in chunks of 64
constexpr int PITCH   = 196;                 // epilogue gh smem pitch (floats)
constexpr int OFF_HP  = 2 * STAGE;           // hprev tile region (stage 2)
constexpr int SMEM_BYTES = NSTAGE * STAGE;   // 98304 -> 2 CTAs/SM

__device__ __forceinline__ void load_chunk(
    int c, int s, int tid, int bm, int bu, uint32_t sbase,
    const __half* hf, const __half* wf)
{
    const int kk = c * 64;
    const uint32_t stA = sbase + s * STAGE;
    const uint32_t stB = stA + OFF_B;
#pragma unroll
    for (int i = 0; i < 2; i++) {
        int v = tid + i * 256;
        int r = v >> 3, kv = v & 7;
        cp_async16(stA + swz(r * 128 + kv * 16),
                   hf + (size_t)(bm * 64 + r) * 1024 + kk + kv * 8);
    }
#pragma unroll
    for (int i = 0; i < 6; i++) {
        int v = tid + i * 256;
        int j = v >> 3, kv = v & 7;
        int g = j >> 6, u = j & 63;
        cp_async16(stB + swz(j * 128 + kv * 16),
                   wf + (size_t)(g * 1024 + bu * 64 + u) * 1024 + kk + kv * 8);
    }
}

__device__ __forceinline__ void load_frags(
    uint32_t stA, uint32_t stB, int ks, int m0, int n0, int lane,
    uint32_t af[2][4], uint32_t bf[3][4])
{
#pragma unroll
    for (int mt = 0; mt < 2; mt++) {
        int r = m0 + mt * 16 + (lane & 15);
        int kb = ks * 32 + ((lane >> 4) << 4);
        ldsm4(af[mt], stA + swz(r * 128 + kb));
    }
#pragma unroll
    for (int p = 0; p < 3; p++) {
        int r = n0 + p * 16 + (lane & 7) + ((lane & 16) ? 8 : 0);
        int kb = ks * 32 + ((lane & 8) ? 16 : 0);
        ldsm4(bf[p], stB + swz(r * 128 + kb));
    }
}

__global__ __launch_bounds__(256, 2) void gru_step_kernel(
    const float* __restrict__ hprev,
    const __half* __restrict__ hf,
    float* __restrict__ hout,
    __half* __restrict__ hfo,
    const __half* __restrict__ wf,
    const float* __restrict__ teacher, int t,
    const float* __restrict__ b_hh, const float* __restrict__ w_ih,
    const float* __restrict__ b_ih, const float* __restrict__ w_out,
    float* __restrict__ partial)
{
    extern __shared__ __align__(1024) char smem[];
    const uint32_t sbase = smem_u32(smem);
    const int tid = threadIdx.x;
    const int lane = tid & 31, wid = tid >> 5;
    const int bm = blockIdx.x, bu = blockIdx.y;
    const int wm = wid & 1, wn = wid >> 1;   // warp grid 2(m) x 4(n)
    const int m0 = wm * 32, n0 = wn * 48;

    float acc[2][6][4];
#pragma unroll
    for (int a = 0; a < 2; a++)
#pragma unroll
        for (int b = 0; b < 6; b++)
#pragma unroll
            for (int q = 0; q < 4; q++) acc[a][b][q] = 0.0f;

#pragma unroll
    for (int p = 0; p < NSTAGE - 1; p++) {
        load_chunk(p, p, tid, bm, bu, sbase, hf, wf);
        cp_commit();
    }

    int stage = 0;
    for (int c = 0; c < NCHUNK; c++) {
        cp_wait1();
        __syncthreads();

        if (c + NSTAGE - 1 < NCHUNK) {
            int s = stage + (NSTAGE - 1);
            if (s >= NSTAGE) s -= NSTAGE;
            load_chunk(c + NSTAGE - 1, s, tid, bm, bu, sbase, hf, wf);
        } else if (c == NCHUNK - 1) {
            // stage 2 dead past this sync: prefetch hprev tile (64x64 fp32)
#pragma unroll
            for (int i = 0; i < 4; i++) {
                int v = tid + i * 256;
                int r = v >> 4, cb = v & 15;
                cp_async16(sbase + OFF_HP + r * 256 + cb * 16,
                           hprev + (size_t)(bm * 64 + r) * 1024 + bu * 64 + cb * 4);
            }
        }
        cp_commit();

        const uint32_t stA = sbase + stage * STAGE;
        const uint32_t stB = stA + OFF_B;

        uint32_t af[2][2][4], bf[2][3][4];
        load_frags(stA, stB, 0, m0, n0, lane, af[0], bf[0]);
#pragma unroll
        for (int ks = 0; ks < 4; ks++) {
            const int cb = ks & 1, nb = cb ^ 1;
            if (ks < 3)
                load_frags(stA, stB, ks + 1, m0, n0, lane, af[nb], bf[nb]);
#pragma unroll
            for (int mt = 0; mt < 2; mt++)
#pragma unroll
                for (int p = 0; p < 3; p++) {
                    mma16816(acc[mt][2 * p],     af[cb][mt], &bf[cb][p][0]);
                    mma16816(acc[mt][2 * p + 1], af[cb][mt], &bf[cb][p][2]);
                }
        }
        if (++stage == NSTAGE) stage = 0;
    }
    cp_wait0();
    __syncthreads();

    float* ghs = (float*)smem;
    const float* hps = (const float*)(smem + OFF_HP);
#pragma unroll
    for (int mt = 0; mt < 2; mt++)
#pragma unroll
        for (int nf = 0; nf < 6; nf++) {
            int row = m0 + mt * 16 + (lane >> 2);
            int col = n0 + nf * 8 + 2 * (lane & 3);
            *(float2*)&ghs[row * PITCH + col] =
                make_float2(acc[mt][nf][0], acc[mt][nf][1]);
            *(float2*)&ghs[(row + 8) * PITCH + col] =
                make_float2(acc[mt][nf][2], acc[mt][nf][3]);
        }
    __syncthreads();

    {
        const int u = tid & 63;
        const int rgrp = tid >> 6;
        const int col = bu * 64 + u;

        const float bhr = b_hh[col], bhz = b_hh[HH + col], bhn = b_hh[2 * HH + col];
        const float wr0 = w_ih[2 * col],            wr1 = w_ih[2 * col + 1];
        const float wz0 = w_ih[2 * (HH + col)],     wz1 = w_ih[2 * (HH + col) + 1];
        const float wn0 = w_ih[2 * (2 * HH + col)], wn1 = w_ih[2 * (2 * HH + col) + 1];
        const float bir = b_ih[col], biz = b_ih[HH + col], bin_ = b_ih[2 * HH + col];

#pragma unroll 4
        for (int k = 0; k < 16; k++) {
            const int r = rgrp + 4 * k;
            const int rg = bm * 64 + r;
            float p0 = 0.0f, p1 = 0.0f;
            if (t > 0) {
                size_t to = ((size_t)rg * TT + (t - 1)) * 2;
                p0 = teacher[to]; p1 = teacher[to + 1];
            }
            float hr = ghs[r * PITCH + u]       + bhr;
            float hz = ghs[r * PITCH + 64 + u]  + bhz;
            float hn = ghs[r * PITCH + 128 + u] + bhn;
            float rv = sigmoidf_(wr0 * p0 + wr1 * p1 + bir + hr);
            float zz = sigmoidf_(wz0 * p0 + wz1 * p1 + biz + hz);
            float nn = tanh_fast(wn0 * p0 + wn1 * p1 + bin_ + rv * hn);
            float h = hps[r * 64 + u];
            float hv = (1.0f - zz) * nn + zz * h;

            size_t go = (size_t)rg * HH + col;
            hout[go] = hv;
            hfo[go]  = __float2half(hv);
            ghs[r * PITCH + u] = hv;
        }
    }
    __syncthreads();

    if (tid < 128) {
        const int r = tid >> 1;
        const int half = tid & 1;
        const int rg = bm * 64 + r;
        const float* hvrow = &ghs[r * PITCH + half * 32];
        float s0 = 0.0f, s1 = 0.0f;
#pragma unroll
        for (int u = 0; u < 32; u += 4) {
            float4 hv4 = *(const float4*)(hvrow + u);
            const int col = bu * 64 + half * 32 + u;
            s0 += hv4.x * w_out[col]     + hv4.y * w_out[col + 1]
                + hv4.z * w_out[col + 2] + hv4.w * w_out[col + 3];
            s1 += hv4.x * w_out[HH + col]     + hv4.y * w_out[HH + col + 1]
                + hv4.z * w_out[HH + col + 2] + hv4.w * w_out[HH + col + 3];
        }
        s0 += __shfl_xor_sync(0xFFFFFFFFu, s0, 1);
        s1 += __shfl_xor_sync(0xFFFFFFFFu, s1, 1);
        if (half == 0) {
            size_t pidx = (((size_t)rg * TT + t) * 2) * 16 + bu;
            partial[pidx]      = s0;
            partial[pidx + 16] = s1;
        }
    }
}

// ===========================================================================
// h0 HMMA kernel: h0 = tanh(ev @ w_init^T + b_init).
// Also converts w_hh -> fp16 in the shadow of its pipeline prologue
// (each of 512 CTAs converts a 1536-float4 slice while stages 0-1 fly).
// ===========================================================================
constexpr int H0_STAGE = 24576;              // A 8KB + B 16KB
constexpr int H0_OFF_B = 8192;
constexpr int H0_SMEM  = NSTAGE * H0_STAGE;  // 73728
constexpr int WHH_VEC4 = 3 * HH * HH / 4;    // 786432 float4
constexpr int H0_CTAS  = (BB / 64) * (HH / 128);   // 512
constexpr int WHH_PER_CTA = WHH_VEC4 / H0_CTAS;    // 1536 (6 per thread)

__device__ __forceinline__ void h0_load_chunk(
    int c, int s, int tid, int bm, int bn, uint32_t sbase,
    const __half* evf, const __half* wif)
{
    const int kk = c * 64;
    const uint32_t stA = sbase + s * H0_STAGE;
    const uint32_t stB = stA + H0_OFF_B;
#pragma unroll
    for (int i = 0; i < 2; i++) {
        int v = tid + i * 256;
        int r = v >> 3, kv = v & 7;
        cp_async16(stA + swz(r * 128 + kv * 16),
                   evf + (size_t)(bm * 64 + r) * 1024 + kk + kv * 8);
    }
#pragma unroll
    for (int i = 0; i < 4; i++) {
        int v = tid + i * 256;
        int j = v >> 3, kv = v & 7;
        cp_async16(stB + swz(j * 128 + kv * 16),
                   wif + (size_t)(bn * 128 + j) * 1024 + kk + kv * 8);
    }
}

__global__ __launch_bounds__(256, 2) void h0_kernel(
    const __half* __restrict__ evf, const __half* __restrict__ wif,
    const float* __restrict__ b_init,
    float* __restrict__ hout, __half* __restrict__ hfo,
    const float4* __restrict__ w_hh, __half* __restrict__ wf)
{
    extern __shared__ __align__(1024) char smem[];
    const uint32_t sbase = smem_u32(smem);
    const int tid = threadIdx.x;
    const int lane = tid & 31, wid = tid >> 5;
    const int bm = blockIdx.x, bn = blockIdx.y;
    const int wm = wid & 1, wn = wid >> 1;
    const int m0 = wm * 32, n0 = wn * 32;

    float acc[2][4][4];
#pragma unroll
    for (int a = 0; a < 2; a++)
#pragma unroll
        for (int b = 0; b < 4; b++)
#pragma unroll
            for (int q = 0; q < 4; q++) acc[a][b][q] = 0.0f;

#pragma unroll
    for (int p = 0; p < NSTAGE - 1; p++) {
        h0_load_chunk(p, p, tid, bm, bn, sbase, evf, wif);
        cp_commit();
    }

    // --- w_hh -> fp16 conversion in the prologue shadow (stages 0-1 in L2) ---
    {
        const int cta = bm * (HH / 128) + bn;            // 0..511
        const int base = cta * WHH_PER_CTA;              // float4 index
#pragma unroll
        for (int i = 0; i < WHH_PER_CTA / 256; i++) {    // 6 per thread
            int j = base + tid + i * 256;
            float4 v = w_hh[j];
            __half2 lo = __floats2half2_rn(v.x, v.y);
            __half2 hi = __floats2half2_rn(v.z, v.w);
            *(__half2*)(wf + (size_t)j * 4)     = lo;
            *(__half2*)(wf + (size_t)j * 4 + 2) = hi;
        }
    }

    int stage = 0;
    for (int c = 0; c < NCHUNK; c++) {
        cp_wait1();
        __syncthreads();

        if (c + NSTAGE - 1 < NCHUNK) {
            int s = stage + (NSTAGE - 1);
            if (s >= NSTAGE) s -= NSTAGE;
            h0_load_chunk(c + NSTAGE - 1, s, tid, bm, bn, sbase, evf, wif);
        }
        cp_commit();

        const uint32_t stA = sbase + stage * H0_STAGE;
        const uint32_t stB = stA + H0_OFF_B;
#pragma unroll
        for (int ks = 0; ks < 4; ks++) {
            uint32_t af[2][4], bf[2][4];
#pragma unroll
            for (int mt = 0; mt < 2; mt++) {
                int r = m0 + mt * 16 + (lane & 15);
                int kb = ks * 32 + ((lane >> 4) << 4);
                ldsm4(af[mt], stA + swz(r * 128 + kb));
            }
#pragma unroll
            for (int p = 0; p < 2; p++) {
                int r = n0 + p * 16 + (lane & 7) + ((lane & 16) ? 8 : 0);
                int kb = ks * 32 + ((lane & 8) ? 16 : 0);
                ldsm4(bf[p], stB + swz(r * 128 + kb));
            }
#pragma unroll
            for (int mt = 0; mt < 2; mt++)
#pragma unroll
                for (int p = 0; p < 2; p++) {
                    mma16816(acc[mt][2 * p],     af[mt], &bf[p][0]);
                    mma16816(acc[mt][2 * p + 1], af[mt], &bf[p][2]);
                }
        }
        if (++stage == NSTAGE) stage = 0;
    }

#pragma unroll
    for (int mt = 0; mt < 2; mt++)
#pragma unroll
        for (int nf = 0; nf < 4; nf++) {
            int row = m0 + mt * 16 + (lane >> 2);
            int col = n0 + nf * 8 + 2 * (lane & 3);
            int gcol = bn * 128 + col;
            float b0 = b_init[gcol], b1 = b_init[gcol + 1];
#pragma unroll
            for (int hrow = 0; hrow < 2; hrow++) {
                int rg = bm * 64 + row + hrow * 8;
                float v0 = tanh_fast(acc[mt][nf][2 * hrow]     + b0);
                float v1 = tanh_fast(acc[mt][nf][2 * hrow + 1] + b1);
                size_t go = (size_t)rg * 1024 + gcol;
                *(float2*)(hout + go) = make_float2(v0, v1);
                __half2 hv2; hv2.x = __float2half(v0); hv2.y = __float2half(v1);
                *(__half2*)(hfo + go) = hv2;
            }
        }
}

// ===========================================================================
// Fused fp32->fp16 conversion for w_init + ev (w_hh now inside h0_kernel)
// ===========================================================================
constexpr int CV_N2 = HH * DD / 4;           // w_init vec4 count (262144)
constexpr int CV_N3 = BB * DD / 4;           // ev    vec4 count (1048576)
constexpr int CV_TOTAL = CV_N2 + CV_N3;

__global__ void convert_all_kernel(
    const float4* __restrict__ w_init, const float4* __restrict__ ev,
    __half* __restrict__ wif, __half* __restrict__ evf)
{
    int i = blockIdx.x * 256 + threadIdx.x;
    if (i >= CV_TOTAL) return;
    const float4* src;
    __half* dst;
    int j;
    if (i < CV_N2) { src = w_init; dst = wif; j = i; }
    else           { src = ev;     dst = evf; j = i - CV_N2; }
    float4 v = src[j];
    __half2 lo = __floats2half2_rn(v.x, v.y);
    __half2 hi = __floats2half2_rn(v.z, v.w);
    *(__half2*)(dst + (size_t)j * 4)     = lo;
    *(__half2*)(dst + (size_t)j * 4 + 2) = hi;
}

// reduce 16 partial slots per (b,t,c), add b_out, write deltas + cumsum pos
__global__ void finalize_kernel(const float* __restrict__ partial,
                                const float* __restrict__ b_out,
                                float* __restrict__ deltas,
                                float* __restrict__ pos)
{
    int idx = blockIdx.x * 256 + threadIdx.x;
    if (idx >= BB * 2) return;
    int b = idx >> 1, c = idx & 1;
    const float bo = b_out[c];
    float acc = 0.0f;
    for (int t = 0; t < TT; t++) {
        const float4* p = (const float4*)(partial + (((size_t)b * TT + t) * 2 + c) * 16);
        float s = bo;
#pragma unroll
        for (int i = 0; i < 4; i++) {
            float4 v = p[i];
            s += v.x + v.y + v.z + v.w;
        }
        size_t o = ((size_t)b * TT + t) * 2 + c;
        deltas[o] = s;
        acc += s;
        pos[o] = acc;
    }
}

// ---------------------------------------------------------------------------
// kernel_launch (graph-capturable, allocation-free)
// ---------------------------------------------------------------------------
extern "C" void kernel_launch(void* const* d_in, const int* in_sizes, int n_in,
                              void* d_out, int out_size)
{
    const float* ev     = (const float*)d_in[0];
    const float* teach  = (const float*)d_in[1];
    const float* w_init = (const float*)d_in[2];
    const float* b_init = (const float*)d_in[3];
    const float* w_ih   = (const float*)d_in[4];
    const float* w_hh   = (const float*)d_in[5];
    const float* b_ih   = (const float*)d_in[6];
    const float* b_hh   = (const float*)d_in[7];
    const float* w_out  = (const float*)d_in[8];
    const float* b_out  = (const float*)d_in[9];
    float* out = (float*)d_out;

    float* hbase;
    __half *hfb, *wfb, *evf, *wif;
    float* partial;
    cudaGetSymbolAddress((void**)&hbase, g_h);
    cudaGetSymbolAddress((void**)&hfb, g_hf);
    cudaGetSymbolAddress((void**)&wfb, g_wf);
    cudaGetSymbolAddress((void**)&evf, g_evf);
    cudaGetSymbolAddress((void**)&wif, g_wif);
    cudaGetSymbolAddress((void**)&partial, g_partial);

    float* hbuf[2] = { hbase, hbase + (size_t)BB * HH };
    __half* hf[2] = { hfb, hfb + (size_t)BB * HH };

    cudaFuncSetAttribute(gru_step_kernel,
                         cudaFuncAttributeMaxDynamicSharedMemorySize, SMEM_BYTES);
    cudaFuncSetAttribute(h0_kernel,
                         cudaFuncAttributeMaxDynamicSharedMemorySize, H0_SMEM);

    // ev + w_init conversions (h0 inputs)
    convert_all_kernel<<<(CV_TOTAL + 255) / 256, 256>>>(
        (const float4*)w_init, (const float4*)ev, wif, evf);

    // h0 = tanh(ev @ w_init^T + b_init) via HMMA; also converts w_hh -> fp16
    // in its prologue shadow. Kernel boundary orders wf before first step.
    h0_kernel<<<dim3(BB / 64, HH / 128), 256, H0_SMEM>>>(
        evf, wif, b_init, hbuf[0], hf[0], (const float4*)w_hh, wfb);

    for (int t = 0; t < TT; t++) {
        int cur = t & 1, nxt = cur ^ 1;
        gru_step_kernel<<<dim3(64, 16), 256, SMEM_BYTES>>>(
            hbuf[cur], hf[cur], hbuf[nxt], hf[nxt],
            wfb, teach, t, b_hh, w_ih, b_ih, w_out, partial);
    }

    finalize_kernel<<<(BB * 2 + 255) / 256, 256>>>(
        partial, b_out, out, out + (size_t)BB * TT * 2);
}

// round 16
// speedup vs baseline: 1.0036x; 1.0036x over previous
#include <cuda_runtime.h>
#include <cuda_fp16.h>
#include <stdint.h>

// ---------------------------------------------------------------------------
// Problem constants
// ---------------------------------------------------------------------------
constexpr int BB = 4096;   // batch
constexpr int DD = 1024;   // ev_context dim
constexpr int HH = 1024;   // hidden
constexpr int TT = 50;     // timesteps

// ---------------------------------------------------------------------------
// Device scratch (no allocs)
// ---------------------------------------------------------------------------
__device__ float  g_h [2][(size_t)BB * HH];
__device__ __half g_hf[2][(size_t)BB * HH];
__device__ __half g_wf[(size_t)3 * HH * HH];
__device__ __half g_evf[(size_t)BB * DD];
__device__ __half g_wif[(size_t)HH * DD];
__device__ float  g_partial[(size_t)BB * TT * 2 * 16];   // [b][t][c][bu]

__device__ __forceinline__ float sigmoidf_(float x) {
    return 1.0f / (1.0f + __expf(-x));
}
__device__ __forceinline__ float tanh_fast(float x) {
    return 2.0f / (1.0f + __expf(-2.0f * x)) - 1.0f;
}

// ---------------------------------------------------------------------------
// PTX helpers (portable sm_80+ only; compute_103-safe)
// ---------------------------------------------------------------------------
__device__ __forceinline__ uint32_t smem_u32(const void* p) {
    uint32_t a;
    asm("{ .reg .u64 t; cvta.to.shared.u64 t, %1; cvt.u32.u64 %0, t; }"
        : "=r"(a) : "l"(p));
    return a;
}
__device__ __forceinline__ uint32_t swz(uint32_t o) { return o ^ ((o >> 3) & 0x70); }
__device__ __forceinline__ void cp_async16(uint32_t dst, const void* src) {
    asm volatile("cp.async.cg.shared.global [%0], [%1], 16;"
                 :: "r"(dst), "l"(src) : "memory");
}
__device__ __forceinline__ void cp_commit() {
    asm volatile("cp.async.commit_group;" ::: "memory");
}
__device__ __forceinline__ void cp_wait1() {
    asm volatile("cp.async.wait_group 1;" ::: "memory");
}
__device__ __forceinline__ void cp_wait0() {
    asm volatile("cp.async.wait_group 0;" ::: "memory");
}
__device__ __forceinline__ void ldsm4(uint32_t* r, uint32_t a) {
    asm volatile("ldmatrix.sync.aligned.m8n8.x4.shared.b16 {%0,%1,%2,%3}, [%4];"
                 : "=r"(r[0]), "=r"(r[1]), "=r"(r[2]), "=r"(r[3]) : "r"(a));
}
__device__ __forceinline__ void mma16816(float* d, const uint32_t* a, const uint32_t* b) {
    asm volatile(
        "mma.sync.aligned.m16n8k16.row.col.f32.f16.f16.f32 "
        "{%0,%1,%2,%3}, {%4,%5,%6,%7}, {%8,%9}, {%0,%1,%2,%3};"
        : "+f"(d[0]), "+f"(d[1]), "+f"(d[2]), "+f"(d[3])
        : "r"(a[0]), "r"(a[1]), "r"(a[2]), "r"(a[3]), "r"(b[0]), "r"(b[1]));
}

// ===========================================================================
// GRU step kernel (at the legacy-HMMA issue ceiling, model-exact)
// ===========================================================================
constexpr int STAGE   = 32768;
constexpr int OFF_B   = 8192;
constexpr int NSTAGE  = 3;
constexpr int NCHUNK  = 16;                  // K=1024 in chunks of 64
constexpr int PITCH   = 196;                 // epilogue gh smem pitch (floats)
constexpr int OFF_HP  = 2 * STAGE;           // hprev tile region (stage 2)
constexpr int SMEM_BYTES = NSTAGE * STAGE;   // 98304 -> 2 CTAs/SM

__device__ __forceinline__ void load_chunk(
    int c, int s, int tid, int bm, int bu, uint32_t sbase,
    const __half* hf, const __half* wf)
{
    const int kk = c * 64;
    const uint32_t stA = sbase + s * STAGE;
    const uint32_t stB = stA + OFF_B;
#pragma unroll
    for (int i = 0; i < 2; i++) {
        int v = tid + i * 256;
        int r = v >> 3, kv = v & 7;
        cp_async16(stA + swz(r * 128 + kv * 16),
                   hf + (size_t)(bm * 64 + r) * 1024 + kk + kv * 8);
    }
#pragma unroll
    for (int i = 0; i < 6; i++) {
        int v = tid + i * 256;
        int j = v >> 3, kv = v & 7;
        int g = j >> 6, u = j & 63;
        cp_async16(stB + swz(j * 128 + kv * 16),
                   wf + (size_t)(g * 1024 + bu * 64 + u) * 1024 + kk + kv * 8);
    }
}

__device__ __forceinline__ void load_frags(
    uint32_t stA, uint32_t stB, int ks, int m0, int n0, int lane,
    uint32_t af[2][4], uint32_t bf[3][4])
{
#pragma unroll
    for (int mt = 0; mt < 2; mt++) {
        int r = m0 + mt * 16 + (lane & 15);
        int kb = ks * 32 + ((lane >> 4) << 4);
        ldsm4(af[mt], stA + swz(r * 128 + kb));
    }
#pragma unroll
    for (int p = 0; p < 3; p++) {
        int r = n0 + p * 16 + (lane & 7) + ((lane & 16) ? 8 : 0);
        int kb = ks * 32 + ((lane & 8) ? 16 : 0);
        ldsm4(bf[p], stB + swz(r * 128 + kb));
    }
}

__global__ __launch_bounds__(256, 2) void gru_step_kernel(
    const float* __restrict__ hprev,
    const __half* __restrict__ hf,
    float* __restrict__ hout,
    __half* __restrict__ hfo,
    const __half* __restrict__ wf,
    const float* __restrict__ teacher, int t,
    const float* __restrict__ b_hh, const float* __restrict__ w_ih,
    const float* __restrict__ b_ih, const float* __restrict__ w_out,
    float* __restrict__ partial)
{
    extern __shared__ __align__(1024) char smem[];
    const uint32_t sbase = smem_u32(smem);
    const int tid = threadIdx.x;
    const int lane = tid & 31, wid = tid >> 5;
    const int bm = blockIdx.x, bu = blockIdx.y;
    const int wm = wid & 1, wn = wid >> 1;   // warp grid 2(m) x 4(n)
    const int m0 = wm * 32, n0 = wn * 48;

    float acc[2][6][4];
#pragma unroll
    for (int a = 0; a < 2; a++)
#pragma unroll
        for (int b = 0; b < 6; b++)
#pragma unroll
            for (int q = 0; q < 4; q++) acc[a][b][q] = 0.0f;

#pragma unroll
    for (int p = 0; p < NSTAGE - 1; p++) {
        load_chunk(p, p, tid, bm, bu, sbase, hf, wf);
        cp_commit();
    }

    int stage = 0;
    for (int c = 0; c < NCHUNK; c++) {
        cp_wait1();
        __syncthreads();

        if (c + NSTAGE - 1 < NCHUNK) {
            int s = stage + (NSTAGE - 1);
            if (s >= NSTAGE) s -= NSTAGE;
            load_chunk(c + NSTAGE - 1, s, tid, bm, bu, sbase, hf, wf);
        } else if (c == NCHUNK - 1) {
            // stage 2 dead past this sync: prefetch hprev tile (64x64 fp32)
#pragma unroll
            for (int i = 0; i < 4; i++) {
                int v = tid + i * 256;
                int r = v >> 4, cb = v & 15;
                cp_async16(sbase + OFF_HP + r * 256 + cb * 16,
                           hprev + (size_t)(bm * 64 + r) * 1024 + bu * 64 + cb * 4);
            }
        }
        cp_commit();

        const uint32_t stA = sbase + stage * STAGE;
        const uint32_t stB = stA + OFF_B;

        uint32_t af[2][2][4], bf[2][3][4];
        load_frags(stA, stB, 0, m0, n0, lane, af[0], bf[0]);
#pragma unroll
        for (int ks = 0; ks < 4; ks++) {
            const int cb = ks & 1, nb = cb ^ 1;
            if (ks < 3)
                load_frags(stA, stB, ks + 1, m0, n0, lane, af[nb], bf[nb]);
#pragma unroll
            for (int mt = 0; mt < 2; mt++)
#pragma unroll
                for (int p = 0; p < 3; p++) {
                    mma16816(acc[mt][2 * p],     af[cb][mt], &bf[cb][p][0]);
                    mma16816(acc[mt][2 * p + 1], af[cb][mt], &bf[cb][p][2]);
                }
        }
        if (++stage == NSTAGE) stage = 0;
    }
    cp_wait0();
    __syncthreads();

    float* ghs = (float*)smem;
    const float* hps = (const float*)(smem + OFF_HP);
#pragma unroll
    for (int mt = 0; mt < 2; mt++)
#pragma unroll
        for (int nf = 0; nf < 6; nf++) {
            int row = m0 + mt * 16 + (lane >> 2);
            int col = n0 + nf * 8 + 2 * (lane & 3);
            *(float2*)&ghs[row * PITCH + col] =
                make_float2(acc[mt][nf][0], acc[mt][nf][1]);
            *(float2*)&ghs[(row + 8) * PITCH + col] =
                make_float2(acc[mt][nf][2], acc[mt][nf][3]);
        }
    __syncthreads();

    {
        const int u = tid & 63;
        const int rgrp = tid >> 6;
        const int col = bu * 64 + u;

        const float bhr = b_hh[col], bhz = b_hh[HH + col], bhn = b_hh[2 * HH + col];
        const float wr0 = w_ih[2 * col],            wr1 = w_ih[2 * col + 1];
        const float wz0 = w_ih[2 * (HH + col)],     wz1 = w_ih[2 * (HH + col) + 1];
        const float wn0 = w_ih[2 * (2 * HH + col)], wn1 = w_ih[2 * (2 * HH + col) + 1];
        const float bir = b_ih[col], biz = b_ih[HH + col], bin_ = b_ih[2 * HH + col];

#pragma unroll 4
        for (int k = 0; k < 16; k++) {
            const int r = rgrp + 4 * k;
            const int rg = bm * 64 + r;
            float p0 = 0.0f, p1 = 0.0f;
            if (t > 0) {
                size_t to = ((size_t)rg * TT + (t - 1)) * 2;
                p0 = teacher[to]; p1 = teacher[to + 1];
            }
            float hr = ghs[r * PITCH + u]       + bhr;
            float hz = ghs[r * PITCH + 64 + u]  + bhz;
            float hn = ghs[r * PITCH + 128 + u] + bhn;
            float rv = sigmoidf_(wr0 * p0 + wr1 * p1 + bir + hr);
            float zz = sigmoidf_(wz0 * p0 + wz1 * p1 + biz + hz);
            float nn = tanh_fast(wn0 * p0 + wn1 * p1 + bin_ + rv * hn);
            float h = hps[r * 64 + u];
            float hv = (1.0f - zz) * nn + zz * h;

            size_t go = (size_t)rg * HH + col;
            hout[go] = hv;
            hfo[go]  = __float2half(hv);
            ghs[r * PITCH + u] = hv;
        }
    }
    __syncthreads();

    if (tid < 128) {
        const int r = tid >> 1;
        const int half = tid & 1;
        const int rg = bm * 64 + r;
        const float* hvrow = &ghs[r * PITCH + half * 32];
        float s0 = 0.0f, s1 = 0.0f;
#pragma unroll
        for (int u = 0; u < 32; u += 4) {
            float4 hv4 = *(const float4*)(hvrow + u);
            const int col = bu * 64 + half * 32 + u;
            s0 += hv4.x * w_out[col]     + hv4.y * w_out[col + 1]
                + hv4.z * w_out[col + 2] + hv4.w * w_out[col + 3];
            s1 += hv4.x * w_out[HH + col]     + hv4.y * w_out[HH + col + 1]
                + hv4.z * w_out[HH + col + 2] + hv4.w * w_out[HH + col + 3];
        }
        s0 += __shfl_xor_sync(0xFFFFFFFFu, s0, 1);
        s1 += __shfl_xor_sync(0xFFFFFFFFu, s1, 1);
        if (half == 0) {
            size_t pidx = (((size_t)rg * TT + t) * 2) * 16 + bu;
            partial[pidx]      = s0;
            partial[pidx + 16] = s1;
        }
    }
}

// ===========================================================================
// h0 HMMA kernel: h0 = tanh(ev @ w_init^T + b_init)
// ===========================================================================
constexpr int H0_STAGE = 24576;              // A 8KB + B 16KB
constexpr int H0_OFF_B = 8192;
constexpr int H0_SMEM  = NSTAGE * H0_STAGE;  // 73728

__device__ __forceinline__ void h0_load_chunk(
    int c, int s, int tid, int bm, int bn, uint32_t sbase,
    const __half* evf, const __half* wif)
{
    const int kk = c * 64;
    const uint32_t stA = sbase + s * H0_STAGE;
    const uint32_t stB = stA + H0_OFF_B;
#pragma unroll
    for (int i = 0; i < 2; i++) {
        int v = tid + i * 256;
        int r = v >> 3, kv = v & 7;
        cp_async16(stA + swz(r * 128 + kv * 16),
                   evf + (size_t)(bm * 64 + r) * 1024 + kk + kv * 8);
    }
#pragma unroll
    for (int i = 0; i < 4; i++) {
        int v = tid + i * 256;
        int j = v >> 3, kv = v & 7;
        cp_async16(stB + swz(j * 128 + kv * 16),
                   wif + (size_t)(bn * 128 + j) * 1024 + kk + kv * 8);
    }
}

__global__ __launch_bounds__(256, 2) void h0_kernel(
    const __half* __restrict__ evf, const __half* __restrict__ wif,
    const float* __restrict__ b_init,
    float* __restrict__ hout, __half* __restrict__ hfo)
{
    extern __shared__ __align__(1024) char smem[];
    const uint32_t sbase = smem_u32(smem);
    const int tid = threadIdx.x;
    const int lane = tid & 31, wid = tid >> 5;
    const int bm = blockIdx.x, bn = blockIdx.y;
    const int wm = wid & 1, wn = wid >> 1;
    const int m0 = wm * 32, n0 = wn * 32;

    float acc[2][4][4];
#pragma unroll
    for (int a = 0; a < 2; a++)
#pragma unroll
        for (int b = 0; b < 4; b++)
#pragma unroll
            for (int q = 0; q < 4; q++) acc[a][b][q] = 0.0f;

#pragma unroll
    for (int p = 0; p < NSTAGE - 1; p++) {
        h0_load_chunk(p, p, tid, bm, bn, sbase, evf, wif);
        cp_commit();
    }

    int stage = 0;
    for (int c = 0; c < NCHUNK; c++) {
        cp_wait1();
        __syncthreads();

        if (c + NSTAGE - 1 < NCHUNK) {
            int s = stage + (NSTAGE - 1);
            if (s >= NSTAGE) s -= NSTAGE;
            h0_load_chunk(c + NSTAGE - 1, s, tid, bm, bn, sbase, evf, wif);
        }
        cp_commit();

        const uint32_t stA = sbase + stage * H0_STAGE;
        const uint32_t stB = stA + H0_OFF_B;
#pragma unroll
        for (int ks = 0; ks < 4; ks++) {
            uint32_t af[2][4], bf[2][4];
#pragma unroll
            for (int mt = 0; mt < 2; mt++) {
                int r = m0 + mt * 16 + (lane & 15);
                int kb = ks * 32 + ((lane >> 4) << 4);
                ldsm4(af[mt], stA + swz(r * 128 + kb));
            }
#pragma unroll
            for (int p = 0; p < 2; p++) {
                int r = n0 + p * 16 + (lane & 7) + ((lane & 16) ? 8 : 0);
                int kb = ks * 32 + ((lane & 8) ? 16 : 0);
                ldsm4(bf[p], stB + swz(r * 128 + kb));
            }
#pragma unroll
            for (int mt = 0; mt < 2; mt++)
#pragma unroll
                for (int p = 0; p < 2; p++) {
                    mma16816(acc[mt][2 * p],     af[mt], &bf[p][0]);
                    mma16816(acc[mt][2 * p + 1], af[mt], &bf[p][2]);
                }
        }
        if (++stage == NSTAGE) stage = 0;
    }

#pragma unroll
    for (int mt = 0; mt < 2; mt++)
#pragma unroll
        for (int nf = 0; nf < 4; nf++) {
            int row = m0 + mt * 16 + (lane >> 2);
            int col = n0 + nf * 8 + 2 * (lane & 3);
            int gcol = bn * 128 + col;
            float b0 = b_init[gcol], b1 = b_init[gcol + 1];
#pragma unroll
            for (int hrow = 0; hrow < 2; hrow++) {
                int rg = bm * 64 + row + hrow * 8;
                float v0 = tanh_fast(acc[mt][nf][2 * hrow]     + b0);
                float v1 = tanh_fast(acc[mt][nf][2 * hrow + 1] + b1);
                size_t go = (size_t)rg * 1024 + gcol;
                *(float2*)(hout + go) = make_float2(v0, v1);
                __half2 hv2; hv2.x = __float2half(v0); hv2.y = __float2half(v1);
                *(__half2*)(hfo + go) = hv2;
            }
        }
}

// ===========================================================================
// Fused fp32->fp16 conversion for w_hh + w_init + ev in ONE launch.
// ===========================================================================
constexpr int CV_N1 = 3 * HH * HH / 4;       // w_hh  vec4 count (786432)
constexpr int CV_N2 = HH * DD / 4;           // w_init vec4 count (262144)
constexpr int CV_N3 = BB * DD / 4;           // ev    vec4 count (1048576)
constexpr int CV_TOTAL = CV_N1 + CV_N2 + CV_N3;

__global__ void convert_all_kernel(
    const float4* __restrict__ w_hh, const float4* __restrict__ w_init,
    const float4* __restrict__ ev,
    __half* __restrict__ wf, __half* __restrict__ wif, __half* __restrict__ evf)
{
    int i = blockIdx.x * 256 + threadIdx.x;
    if (i >= CV_TOTAL) return;
    const float4* src;
    __half* dst;
    int j;
    if (i < CV_N1)            { src = w_hh;   dst = wf;  j = i; }
    else if (i < CV_N1+CV_N2) { src = w_init; dst = wif; j = i - CV_N1; }
    else                      { src = ev;     dst = evf; j = i - CV_N1 - CV_N2; }
    float4 v = src[j];
    __half2 lo = __floats2half2_rn(v.x, v.y);
    __half2 hi = __floats2half2_rn(v.z, v.w);
    *(__half2*)(dst + (size_t)j * 4)     = lo;
    *(__half2*)(dst + (size_t)j * 4 + 2) = hi;
}

// reduce 16 partial slots per (b,t,c), add b_out, write deltas + cumsum pos
__global__ void finalize_kernel(const float* __restrict__ partial,
                                const float* __restrict__ b_out,
                                float* __restrict__ deltas,
                                float* __restrict__ pos)
{
    int idx = blockIdx.x * 256 + threadIdx.x;
    if (idx >= BB * 2) return;
    int b = idx >> 1, c = idx & 1;
    const float bo = b_out[c];
    float acc = 0.0f;
    for (int t = 0; t < TT; t++) {
        const float4* p = (const float4*)(partial + (((size_t)b * TT + t) * 2 + c) * 16);
        float s = bo;
#pragma unroll
        for (int i = 0; i < 4; i++) {
            float4 v = p[i];
            s += v.x + v.y + v.z + v.w;
        }
        size_t o = ((size_t)b * TT + t) * 2 + c;
        deltas[o] = s;
        acc += s;
        pos[o] = acc;
    }
}

// ---------------------------------------------------------------------------
// kernel_launch (graph-capturable, allocation-free)
// ---------------------------------------------------------------------------
extern "C" void kernel_launch(void* const* d_in, const int* in_sizes, int n_in,
                              void* d_out, int out_size)
{
    const float* ev     = (const float*)d_in[0];
    const float* teach  = (const float*)d_in[1];
    const float* w_init = (const float*)d_in[2];
    const float* b_init = (const float*)d_in[3];
    const float* w_ih   = (const float*)d_in[4];
    const float* w_hh   = (const float*)d_in[5];
    const float* b_ih   = (const float*)d_in[6];
    const float* b_hh   = (const float*)d_in[7];
    const float* w_out  = (const float*)d_in[8];
    const float* b_out  = (const float*)d_in[9];
    float* out = (float*)d_out;

    float* hbase;
    __half *hfb, *wfb, *evf, *wif;
    float* partial;
    cudaGetSymbolAddress((void**)&hbase, g_h);
    cudaGetSymbolAddress((void**)&hfb, g_hf);
    cudaGetSymbolAddress((void**)&wfb, g_wf);
    cudaGetSymbolAddress((void**)&evf, g_evf);
    cudaGetSymbolAddress((void**)&wif, g_wif);
    cudaGetSymbolAddress((void**)&partial, g_partial);

    float* hbuf[2] = { hbase, hbase + (size_t)BB * HH };
    __half* hf[2] = { hfb, hfb + (size_t)BB * HH };

    cudaFuncSetAttribute(gru_step_kernel,
                         cudaFuncAttributeMaxDynamicSharedMemorySize, SMEM_BYTES);
    cudaFuncSetAttribute(h0_kernel,
                         cudaFuncAttributeMaxDynamicSharedMemorySize, H0_SMEM);

    // all fp16 conversions in one vectorized launch
    convert_all_kernel<<<(CV_TOTAL + 255) / 256, 256>>>(
        (const float4*)w_hh, (const float4*)w_init, (const float4*)ev,
        wfb, wif, evf);

    // h0 = tanh(ev @ w_init^T + b_init) via HMMA; writes fp32 + fp16
    h0_kernel<<<dim3(BB / 64, HH / 128), 256, H0_SMEM>>>(
        evf, wif, b_init, hbuf[0], hf[0]);

    for (int t = 0; t < TT; t++) {
        int cur = t & 1, nxt = cur ^ 1;
        gru_step_kernel<<<dim3(64, 16), 256, SMEM_BYTES>>>(
            hbuf[cur], hf[cur], hbuf[nxt], hf[nxt],
            wfb, teach, t, b_hh, w_ih, b_ih, w_out, partial);
    }

    finalize_kernel<<<(BB * 2 + 255) / 256, 256>>>(
        partial, b_out, out, out + (size_t)BB * TT * 2);
}

// round 17
// speedup vs baseline: 1.0163x; 1.0126x over previous
#include <cuda_runtime.h>
#include <cuda_fp16.h>
#include <stdint.h>

// ---------------------------------------------------------------------------
// Problem constants
// ---------------------------------------------------------------------------
constexpr int BB = 4096;   // batch
constexpr int DD = 1024;   // ev_context dim
constexpr int HH = 1024;   // hidden
constexpr int TT = 50;     // timesteps

// ---------------------------------------------------------------------------
// Device scratch (no allocs)
// ---------------------------------------------------------------------------
__device__ float  g_h [2][(size_t)BB * HH];
__device__ __half g_hf[2][(size_t)BB * HH];
__device__ __half g_wf[(size_t)3 * HH * HH];
__device__ __half g_evf[(size_t)BB * DD];
__device__ __half g_wif[(size_t)HH * DD];
__device__ float  g_partial[(size_t)BB * TT * 2 * 16];   // [b][t][c][bu]

__device__ __forceinline__ float sigmoidf_(float x) {
    return 1.0f / (1.0f + __expf(-x));
}
__device__ __forceinline__ float tanh_fast(float x) {
    return 2.0f / (1.0f + __expf(-2.0f * x)) - 1.0f;
}

// ---------------------------------------------------------------------------
// PTX helpers (portable sm_80+ only; compute_103-safe)
// ---------------------------------------------------------------------------
__device__ __forceinline__ uint32_t smem_u32(const void* p) {
    uint32_t a;
    asm("{ .reg .u64 t; cvta.to.shared.u64 t, %1; cvt.u32.u64 %0, t; }"
        : "=r"(a) : "l"(p));
    return a;
}
__device__ __forceinline__ uint32_t swz(uint32_t o) { return o ^ ((o >> 3) & 0x70); }
__device__ __forceinline__ void cp_async16(uint32_t dst, const void* src) {
    asm volatile("cp.async.cg.shared.global [%0], [%1], 16;"
                 :: "r"(dst), "l"(src) : "memory");
}
__device__ __forceinline__ void cp_commit() {
    asm volatile("cp.async.commit_group;" ::: "memory");
}
__device__ __forceinline__ void cp_wait1() {
    asm volatile("cp.async.wait_group 1;" ::: "memory");
}
__device__ __forceinline__ void cp_wait0() {
    asm volatile("cp.async.wait_group 0;" ::: "memory");
}
__device__ __forceinline__ void ldsm4(uint32_t* r, uint32_t a) {
    asm volatile("ldmatrix.sync.aligned.m8n8.x4.shared.b16 {%0,%1,%2,%3}, [%4];"
                 : "=r"(r[0]), "=r"(r[1]), "=r"(r[2]), "=r"(r[3]) : "r"(a));
}
__device__ __forceinline__ void mma16816(float* d, const uint32_t* a, const uint32_t* b) {
    asm volatile(
        "mma.sync.aligned.m16n8k16.row.col.f32.f16.f16.f32 "
        "{%0,%1,%2,%3}, {%4,%5,%6,%7}, {%8,%9}, {%0,%1,%2,%3};"
        : "+f"(d[0]), "+f"(d[1]), "+f"(d[2]), "+f"(d[3])
        : "r"(a[0]), "r"(a[1]), "r"(a[2]), "r"(a[3]), "r"(b[0]), "r"(b[1]));
}

// ===========================================================================
// GRU step kernel (at the legacy-HMMA issue ceiling, model-exact)
// ===========================================================================
constexpr int STAGE   = 32768;
constexpr int OFF_B   = 8192;
constexpr int NSTAGE  = 3;
constexpr int NCHUNK  = 16;                  // K=1024 in chunks of 64
constexpr int PITCH   = 196;                 // epilogue gh smem pitch (floats)
constexpr int OFF_HP  = 2 * STAGE;           // hprev tile region (stage 2)
constexpr int SMEM_BYTES = NSTAGE * STAGE;   // 98304 -> 2 CTAs/SM

__device__ __forceinline__ void load_chunk(
    int c, int s, int tid, int bm, int bu, uint32_t sbase,
    const __half* hf, const __half* wf)
{
    const int kk = c * 64;
    const uint32_t stA = sbase + s * STAGE;
    const uint32_t stB = stA + OFF_B;
#pragma unroll
    for (int i = 0; i < 2; i++) {
        int v = tid + i * 256;
        int r = v >> 3, kv = v & 7;
        cp_async16(stA + swz(r * 128 + kv * 16),
                   hf + (size_t)(bm * 64 + r) * 1024 + kk + kv * 8);
    }
#pragma unroll
    for (int i = 0; i < 6; i++) {
        int v = tid + i * 256;
        int j = v >> 3, kv = v & 7;
        int g = j >> 6, u = j & 63;
        cp_async16(stB + swz(j * 128 + kv * 16),
                   wf + (size_t)(g * 1024 + bu * 64 + u) * 1024 + kk + kv * 8);
    }
}

__device__ __forceinline__ void load_frags(
    uint32_t stA, uint32_t stB, int ks, int m0, int n0, int lane,
    uint32_t af[2][4], uint32_t bf[3][4])
{
#pragma unroll
    for (int mt = 0; mt < 2; mt++) {
        int r = m0 + mt * 16 + (lane & 15);
        int kb = ks * 32 + ((lane >> 4) << 4);
        ldsm4(af[mt], stA + swz(r * 128 + kb));
    }
#pragma unroll
    for (int p = 0; p < 3; p++) {
        int r = n0 + p * 16 + (lane & 7) + ((lane & 16) ? 8 : 0);
        int kb = ks * 32 + ((lane & 8) ? 16 : 0);
        ldsm4(bf[p], stB + swz(r * 128 + kb));
    }
}

__global__ __launch_bounds__(256, 2) void gru_step_kernel(
    const float* __restrict__ hprev,
    const __half* __restrict__ hf,
    float* __restrict__ hout,
    __half* __restrict__ hfo,
    const __half* __restrict__ wf,
    const float* __restrict__ teacher, int t,
    const float* __restrict__ b_hh, const float* __restrict__ w_ih,
    const float* __restrict__ b_ih, const float* __restrict__ w_out,
    float* __restrict__ partial)
{
    extern __shared__ __align__(1024) char smem[];
    const uint32_t sbase = smem_u32(smem);
    const int tid = threadIdx.x;
    const int lane = tid & 31, wid = tid >> 5;
    const int bm = blockIdx.x, bu = blockIdx.y;
    const int wm = wid & 1, wn = wid >> 1;   // warp grid 2(m) x 4(n)
    const int m0 = wm * 32, n0 = wn * 48;

    float acc[2][6][4];
#pragma unroll
    for (int a = 0; a < 2; a++)
#pragma unroll
        for (int b = 0; b < 6; b++)
#pragma unroll
            for (int q = 0; q < 4; q++) acc[a][b][q] = 0.0f;

#pragma unroll
    for (int p = 0; p < NSTAGE - 1; p++) {
        load_chunk(p, p, tid, bm, bu, sbase, hf, wf);
        cp_commit();
    }

    int stage = 0;
    for (int c = 0; c < NCHUNK; c++) {
        cp_wait1();
        __syncthreads();

        if (c + NSTAGE - 1 < NCHUNK) {
            int s = stage + (NSTAGE - 1);
            if (s >= NSTAGE) s -= NSTAGE;
            load_chunk(c + NSTAGE - 1, s, tid, bm, bu, sbase, hf, wf);
        } else if (c == NCHUNK - 1) {
            // stage 2 dead past this sync: prefetch hprev tile (64x64 fp32)
#pragma unroll
            for (int i = 0; i < 4; i++) {
                int v = tid + i * 256;
                int r = v >> 4, cb = v & 15;
                cp_async16(sbase + OFF_HP + r * 256 + cb * 16,
                           hprev + (size_t)(bm * 64 + r) * 1024 + bu * 64 + cb * 4);
            }
        }
        cp_commit();

        const uint32_t stA = sbase + stage * STAGE;
        const uint32_t stB = stA + OFF_B;

        uint32_t af[2][2][4], bf[2][3][4];
        load_frags(stA, stB, 0, m0, n0, lane, af[0], bf[0]);
#pragma unroll
        for (int ks = 0; ks < 4; ks++) {
            const int cb = ks & 1, nb = cb ^ 1;
            if (ks < 3)
                load_frags(stA, stB, ks + 1, m0, n0, lane, af[nb], bf[nb]);
#pragma unroll
            for (int mt = 0; mt < 2; mt++)
#pragma unroll
                for (int p = 0; p < 3; p++) {
                    mma16816(acc[mt][2 * p],     af[cb][mt], &bf[cb][p][0]);
                    mma16816(acc[mt][2 * p + 1], af[cb][mt], &bf[cb][p][2]);
                }
        }
        if (++stage == NSTAGE) stage = 0;
    }
    cp_wait0();
    __syncthreads();

    float* ghs = (float*)smem;
    const float* hps = (const float*)(smem + OFF_HP);
#pragma unroll
    for (int mt = 0; mt < 2; mt++)
#pragma unroll
        for (int nf = 0; nf < 6; nf++) {
            int row = m0 + mt * 16 + (lane >> 2);
            int col = n0 + nf * 8 + 2 * (lane & 3);
            *(float2*)&ghs[row * PITCH + col] =
                make_float2(acc[mt][nf][0], acc[mt][nf][1]);
            *(float2*)&ghs[(row + 8) * PITCH + col] =
                make_float2(acc[mt][nf][2], acc[mt][nf][3]);
        }
    __syncthreads();

    {
        const int u = tid & 63;
        const int rgrp = tid >> 6;
        const int col = bu * 64 + u;

        const float bhr = b_hh[col], bhz = b_hh[HH + col], bhn = b_hh[2 * HH + col];
        const float wr0 = w_ih[2 * col],            wr1 = w_ih[2 * col + 1];
        const float wz0 = w_ih[2 * (HH + col)],     wz1 = w_ih[2 * (HH + col) + 1];
        const float wn0 = w_ih[2 * (2 * HH + col)], wn1 = w_ih[2 * (2 * HH + col) + 1];
        const float bir = b_ih[col], biz = b_ih[HH + col], bin_ = b_ih[2 * HH + col];

        // hoisted teacher base: row rg reads teacher[rg*TT + (t-1)] as float2
        const float2* tch = (t > 0)
            ? (const float2*)(teacher + (size_t)(t - 1) * 2) : nullptr;

#pragma unroll 4
        for (int k = 0; k < 16; k++) {
            const int r = rgrp + 4 * k;
            const int rg = bm * 64 + r;
            float p0 = 0.0f, p1 = 0.0f;
            if (tch) {
                float2 pv = tch[(size_t)rg * TT];   // = teacher[(rg*TT+t-1)*2 ..]
                p0 = pv.x; p1 = pv.y;
            }
            float hr = ghs[r * PITCH + u]       + bhr;
            float hz = ghs[r * PITCH + 64 + u]  + bhz;
            float hn = ghs[r * PITCH + 128 + u] + bhn;
            float rv = sigmoidf_(wr0 * p0 + wr1 * p1 + bir + hr);
            float zz = sigmoidf_(wz0 * p0 + wz1 * p1 + biz + hz);
            float nn = tanh_fast(wn0 * p0 + wn1 * p1 + bin_ + rv * hn);
            float h = hps[r * 64 + u];
            float hv = (1.0f - zz) * nn + zz * h;

            size_t go = (size_t)rg * HH + col;
            hout[go] = hv;
            hfo[go]  = __float2half(hv);
            ghs[r * PITCH + u] = hv;
        }
    }
    __syncthreads();

    if (tid < 128) {
        const int r = tid >> 1;
        const int half = tid & 1;
        const int rg = bm * 64 + r;
        const float* hvrow = &ghs[r * PITCH + half * 32];
        float s0 = 0.0f, s1 = 0.0f;
#pragma unroll
        for (int u = 0; u < 32; u += 4) {
            float4 hv4 = *(const float4*)(hvrow + u);
            const int col = bu * 64 + half * 32 + u;
            s0 += hv4.x * w_out[col]     + hv4.y * w_out[col + 1]
                + hv4.z * w_out[col + 2] + hv4.w * w_out[col + 3];
            s1 += hv4.x * w_out[HH + col]     + hv4.y * w_out[HH + col + 1]
                + hv4.z * w_out[HH + col + 2] + hv4.w * w_out[HH + col + 3];
        }
        s0 += __shfl_xor_sync(0xFFFFFFFFu, s0, 1);
        s1 += __shfl_xor_sync(0xFFFFFFFFu, s1, 1);
        if (half == 0) {
            size_t pidx = (((size_t)rg * TT + t) * 2) * 16 + bu;
            partial[pidx]      = s0;
            partial[pidx + 16] = s1;
        }
    }
}

// ===========================================================================
// h0 HMMA kernel: h0 = tanh(ev @ w_init^T + b_init)
// ===========================================================================
constexpr int H0_STAGE = 24576;              // A 8KB + B 16KB
constexpr int H0_OFF_B = 8192;
constexpr int H0_SMEM  = NSTAGE * H0_STAGE;  // 73728

__device__ __forceinline__ void h0_load_chunk(
    int c, int s, int tid, int bm, int bn, uint32_t sbase,
    const __half* evf, const __half* wif)
{
    const int kk = c * 64;
    const uint32_t stA = sbase + s * H0_STAGE;
    const uint32_t stB = stA + H0_OFF_B;
#pragma unroll
    for (int i = 0; i < 2; i++) {
        int v = tid + i * 256;
        int r = v >> 3, kv = v & 7;
        cp_async16(stA + swz(r * 128 + kv * 16),
                   evf + (size_t)(bm * 64 + r) * 1024 + kk + kv * 8);
    }
#pragma unroll
    for (int i = 0; i < 4; i++) {
        int v = tid + i * 256;
        int j = v >> 3, kv = v & 7;
        cp_async16(stB + swz(j * 128 + kv * 16),
                   wif + (size_t)(bn * 128 + j) * 1024 + kk + kv * 8);
    }
}

__global__ __launch_bounds__(256, 2) void h0_kernel(
    const __half* __restrict__ evf, const __half* __restrict__ wif,
    const float* __restrict__ b_init,
    float* __restrict__ hout, __half* __restrict__ hfo)
{
    extern __shared__ __align__(1024) char smem[];
    const uint32_t sbase = smem_u32(smem);
    const int tid = threadIdx.x;
    const int lane = tid & 31, wid = tid >> 5;
    const int bm = blockIdx.x, bn = blockIdx.y;
    const int wm = wid & 1, wn = wid >> 1;
    const int m0 = wm * 32, n0 = wn * 32;

    float acc[2][4][4];
#pragma unroll
    for (int a = 0; a < 2; a++)
#pragma unroll
        for (int b = 0; b < 4; b++)
#pragma unroll
            for (int q = 0; q < 4; q++) acc[a][b][q] = 0.0f;

#pragma unroll
    for (int p = 0; p < NSTAGE - 1; p++) {
        h0_load_chunk(p, p, tid, bm, bn, sbase, evf, wif);
        cp_commit();
    }

    int stage = 0;
    for (int c = 0; c < NCHUNK; c++) {
        cp_wait1();
        __syncthreads();

        if (c + NSTAGE - 1 < NCHUNK) {
            int s = stage + (NSTAGE - 1);
            if (s >= NSTAGE) s -= NSTAGE;
            h0_load_chunk(c + NSTAGE - 1, s, tid, bm, bn, sbase, evf, wif);
        }
        cp_commit();

        const uint32_t stA = sbase + stage * H0_STAGE;
        const uint32_t stB = stA + H0_OFF_B;
#pragma unroll
        for (int ks = 0; ks < 4; ks++) {
            uint32_t af[2][4], bf[2][4];
#pragma unroll
            for (int mt = 0; mt < 2; mt++) {
                int r = m0 + mt * 16 + (lane & 15);
                int kb = ks * 32 + ((lane >> 4) << 4);
                ldsm4(af[mt], stA + swz(r * 128 + kb));
            }
#pragma unroll
            for (int p = 0; p < 2; p++) {
                int r = n0 + p * 16 + (lane & 7) + ((lane & 16) ? 8 : 0);
                int kb = ks * 32 + ((lane & 8) ? 16 : 0);
                ldsm4(bf[p], stB + swz(r * 128 + kb));
            }
#pragma unroll
            for (int mt = 0; mt < 2; mt++)
#pragma unroll
                for (int p = 0; p < 2; p++) {
                    mma16816(acc[mt][2 * p],     af[mt], &bf[p][0]);
                    mma16816(acc[mt][2 * p + 1], af[mt], &bf[p][2]);
                }
        }
        if (++stage == NSTAGE) stage = 0;
    }

#pragma unroll
    for (int mt = 0; mt < 2; mt++)
#pragma unroll
        for (int nf = 0; nf < 4; nf++) {
            int row = m0 + mt * 16 + (lane >> 2);
            int col = n0 + nf * 8 + 2 * (lane & 3);
            int gcol = bn * 128 + col;
            float b0 = b_init[gcol], b1 = b_init[gcol + 1];
#pragma unroll
            for (int hrow = 0; hrow < 2; hrow++) {
                int rg = bm * 64 + row + hrow * 8;
                float v0 = tanh_fast(acc[mt][nf][2 * hrow]     + b0);
                float v1 = tanh_fast(acc[mt][nf][2 * hrow + 1] + b1);
                size_t go = (size_t)rg * 1024 + gcol;
                *(float2*)(hout + go) = make_float2(v0, v1);
                __half2 hv2; hv2.x = __float2half(v0); hv2.y = __float2half(v1);
                *(__half2*)(hfo + go) = hv2;
            }
        }
}

// ===========================================================================
// Fused fp32->fp16 conversion for w_hh + w_init + ev in ONE launch.
// ===========================================================================
constexpr int CV_N1 = 3 * HH * HH / 4;       // w_hh  vec4 count (786432)
constexpr int CV_N2 = HH * DD / 4;           // w_init vec4 count (262144)
constexpr int CV_N3 = BB * DD / 4;           // ev    vec4 count (1048576)
constexpr int CV_TOTAL = CV_N1 + CV_N2 + CV_N3;

__global__ void convert_all_kernel(
    const float4* __restrict__ w_hh, const float4* __restrict__ w_init,
    const float4* __restrict__ ev,
    __half* __restrict__ wf, __half* __restrict__ wif, __half* __restrict__ evf)
{
    int i = blockIdx.x * 256 + threadIdx.x;
    if (i >= CV_TOTAL) return;
    const float4* src;
    __half* dst;
    int j;
    if (i < CV_N1)            { src = w_hh;   dst = wf;  j = i; }
    else if (i < CV_N1+CV_N2) { src = w_init; dst = wif; j = i - CV_N1; }
    else                      { src = ev;     dst = evf; j = i - CV_N1 - CV_N2; }
    float4 v = src[j];
    __half2 lo = __floats2half2_rn(v.x, v.y);
    __half2 hi = __floats2half2_rn(v.z, v.w);
    *(__half2*)(dst + (size_t)j * 4)     = lo;
    *(__half2*)(dst + (size_t)j * 4 + 2) = hi;
}

// reduce 16 partial slots per (b,t,c), add b_out, write deltas + cumsum pos
__global__ void finalize_kernel(const float* __restrict__ partial,
                                const float* __restrict__ b_out,
                                float* __restrict__ deltas,
                                float* __restrict__ pos)
{
    int idx = blockIdx.x * 256 + threadIdx.x;
    if (idx >= BB * 2) return;
    int b = idx >> 1, c = idx & 1;
    const float bo = b_out[c];
    float acc = 0.0f;
    for (int t = 0; t < TT; t++) {
        const float4* p = (const float4*)(partial + (((size_t)b * TT + t) * 2 + c) * 16);
        float s = bo;
#pragma unroll
        for (int i = 0; i < 4; i++) {
            float4 v = p[i];
            s += v.x + v.y + v.z + v.w;
        }
        size_t o = ((size_t)b * TT + t) * 2 + c;
        deltas[o] = s;
        acc += s;
        pos[o] = acc;
    }
}

// ---------------------------------------------------------------------------
// kernel_launch (graph-capturable, allocation-free)
// ---------------------------------------------------------------------------
extern "C" void kernel_launch(void* const* d_in, const int* in_sizes, int n_in,
                              void* d_out, int out_size)
{
    const float* ev     = (const float*)d_in[0];
    const float* teach  = (const float*)d_in[1];
    const float* w_init = (const float*)d_in[2];
    const float* b_init = (const float*)d_in[3];
    const float* w_ih   = (const float*)d_in[4];
    const float* w_hh   = (const float*)d_in[5];
    const float* b_ih   = (const float*)d_in[6];
    const float* b_hh   = (const float*)d_in[7];
    const float* w_out  = (const float*)d_in[8];
    const float* b_out  = (const float*)d_in[9];
    float* out = (float*)d_out;

    float* hbase;
    __half *hfb, *wfb, *evf, *wif;
    float* partial;
    cudaGetSymbolAddress((void**)&hbase, g_h);
    cudaGetSymbolAddress((void**)&hfb, g_hf);
    cudaGetSymbolAddress((void**)&wfb, g_wf);
    cudaGetSymbolAddress((void**)&evf, g_evf);
    cudaGetSymbolAddress((void**)&wif, g_wif);
    cudaGetSymbolAddress((void**)&partial, g_partial);

    float* hbuf[2] = { hbase, hbase + (size_t)BB * HH };
    __half* hf[2] = { hfb, hfb + (size_t)BB * HH };

    cudaFuncSetAttribute(gru_step_kernel,
                         cudaFuncAttributeMaxDynamicSharedMemorySize, SMEM_BYTES);
    cudaFuncSetAttribute(h0_kernel,
                         cudaFuncAttributeMaxDynamicSharedMemorySize, H0_SMEM);

    // all fp16 conversions in one vectorized launch
    convert_all_kernel<<<(CV_TOTAL + 255) / 256, 256>>>(
        (const float4*)w_hh, (const float4*)w_init, (const float4*)ev,
        wfb, wif, evf);

    // h0 = tanh(ev @ w_init^T + b_init) via HMMA; writes fp32 + fp16
    h0_kernel<<<dim3(BB / 64, HH / 128), 256, H0_SMEM>>>(
        evf, wif, b_init, hbuf[0], hf[0]);

    for (int t = 0; t < TT; t++) {
        int cur = t & 1, nxt = cur ^ 1;
        gru_step_kernel<<<dim3(64, 16), 256, SMEM_BYTES>>>(
            hbuf[cur], hf[cur], hbuf[nxt], hf[nxt],
            wfb, teach, t, b_hh, w_ih, b_ih, w_out, partial);
    }

    finalize_kernel<<<(BB * 2 + 255) / 256, 256>>>(
        partial, b_out, out, out + (size_t)BB * TT * 2);
}